// round 6
// baseline (speedup 1.0000x reference)
#include <cuda_runtime.h>
#include <math.h>

#define Bsz 32
#define Ssz 512
#define Hsz 1024
#define Osz 1024
#define GRID 148

// ---------------- device scratch (static globals: allowed) ----------------
__device__ float g_xp0[(size_t)Ssz * Bsz * 3 * Hsz];   // layer0 x-projections (s,b,3H)
__device__ float g_h1all[(size_t)Ssz * Bsz * Hsz];     // all layer1 hidden states (s,b,H)
__device__ float g_h0[Bsz * Hsz];
__device__ float g_h1[Bsz * Hsz];
__device__ float g_z0[Bsz * Hsz];
__device__ float g_rh0[Bsz * Hsz];
__device__ float g_z1[Bsz * Hsz];
__device__ float g_rh1[Bsz * Hsz];
__device__ float g_gc1[Bsz * Hsz];
__device__ float g_pz1[Bsz * Hsz];           // raw h1 @ Wh[1][0]^T
__device__ float g_pr1[Bsz * Hsz];           // raw h1 @ Wh[1][1]^T
__device__ float g_partB[4 * Bsz * Hsz];     // K-split partials, layer0 candidate
__device__ float g_partD[4 * Bsz * Hsz];     // K-split partials, layer1 candidate
__device__ unsigned g_barcnt;

__device__ __forceinline__ float sigf(float x) { return 1.f / (1.f + expf(-x)); }

#define FMA16() do { \
    acc[0][0] += a.x*b.x; acc[0][1] += a.x*b.y; acc[0][2] += a.x*b.z; acc[0][3] += a.x*b.w; \
    acc[1][0] += a.y*b.x; acc[1][1] += a.y*b.y; acc[1][2] += a.y*b.z; acc[1][3] += a.y*b.w; \
    acc[2][0] += a.z*b.x; acc[2][1] += a.z*b.y; acc[2][2] += a.z*b.z; acc[2][3] += a.z*b.w; \
    acc[3][0] += a.w*b.x; acc[3][1] += a.w*b.y; acc[3][2] += a.w*b.z; acc[3][3] += a.w*b.w; \
} while (0)

// ---------------- grid barrier (monotonic counter, reset in k_init) ----------------
__device__ __forceinline__ void gridbar(unsigned gen) {
    __syncthreads();
    if (threadIdx.x == 0) {
        __threadfence();                       // publish my writes (also flushes L1D)
        atomicAdd(&g_barcnt, 1u);
        const unsigned tgt = gen * GRID;
        while (*(volatile unsigned*)&g_barcnt < tgt) { }
        __threadfence();                       // flush L1D so we see peers' writes
    }
    __syncthreads();
}

// ---------------- init: unpack h0 (B,L,H) and reset barrier ----------------
__global__ void k_init(const float* __restrict__ h0in) {
    if (blockIdx.x == 0 && threadIdx.x == 0) g_barcnt = 0u;
    int idx = blockIdx.x * blockDim.x + threadIdx.x;  // 0..65535
    int b = idx >> 11;
    int r = idx & 2047;
    int l = r >> 10;
    int i = r & 1023;
    float v = h0in[idx];
    if (l == 0) g_h0[b * Hsz + i] = v;
    else        g_h1[b * Hsz + i] = v;
}

// ---------------- big GEMM: xp0 = x @ Wx[0]^T + bx[0] ----------------
__global__ __launch_bounds__(256) void k_xproj(const float* __restrict__ x,
                                               const float* __restrict__ Wx,
                                               const float* __restrict__ bxp) {
    __shared__ __align__(16) float sm[2048];
    float* As = sm;
    float* Bs = sm + 1024;
    const int tid = threadIdx.x;
    const int bm = blockIdx.y << 6;
    const int bn = blockIdx.x << 6;
    const int lr = tid >> 2;            // 0..63
    const int lk = (tid & 3) << 2;      // 0,4,8,12
    const int mrow = bm + lr;
    const size_t a_off = ((size_t)(mrow & 31) * Ssz + (mrow >> 5)) * Hsz;  // x[b][s][*]
    const size_t b_off = (size_t)(bn + lr) * Hsz;                          // Wx row
    const int tm = (tid >> 4) << 2;
    const int tn = (tid & 15) << 2;
    float acc[4][4] = {};
    for (int k0 = 0; k0 < Hsz; k0 += 16) {
        float4 av = *(const float4*)(x + a_off + k0 + lk);
        float4 bv = *(const float4*)(Wx + b_off + k0 + lk);
        As[(lk + 0) * 64 + lr] = av.x; As[(lk + 1) * 64 + lr] = av.y;
        As[(lk + 2) * 64 + lr] = av.z; As[(lk + 3) * 64 + lr] = av.w;
        Bs[(lk + 0) * 64 + lr] = bv.x; Bs[(lk + 1) * 64 + lr] = bv.y;
        Bs[(lk + 2) * 64 + lr] = bv.z; Bs[(lk + 3) * 64 + lr] = bv.w;
        __syncthreads();
#pragma unroll
        for (int kk = 0; kk < 16; kk++) {
            float4 a = *(const float4*)(As + kk * 64 + tm);
            float4 b = *(const float4*)(Bs + kk * 64 + tn);
            FMA16();
        }
        __syncthreads();
    }
#pragma unroll
    for (int i = 0; i < 4; i++) {
        size_t ro = (size_t)(bm + tm + i) * 3072;
#pragma unroll
        for (int j = 0; j < 4; j++) {
            int n = bn + tn + j;
            g_xp0[ro + n] = acc[i][j] + bxp[n];
        }
    }
}

// ---------------- big GEMM: out = h1all @ Wo^T + bo ----------------
__global__ __launch_bounds__(256) void k_out(const float* __restrict__ Wo,
                                             const float* __restrict__ bo,
                                             float* __restrict__ out) {
    __shared__ __align__(16) float sm[2048];
    float* As = sm;
    float* Bs = sm + 1024;
    const int tid = threadIdx.x;
    const int bm = blockIdx.y << 6;
    const int bn = blockIdx.x << 6;
    const int lr = tid >> 2;
    const int lk = (tid & 3) << 2;
    const size_t a_off = (size_t)(bm + lr) * Hsz;     // h1all row (s*32+b)
    const size_t b_off = (size_t)(bn + lr) * Hsz;     // Wo row
    const int tm = (tid >> 4) << 2;
    const int tn = (tid & 15) << 2;
    float acc[4][4] = {};
    for (int k0 = 0; k0 < Hsz; k0 += 16) {
        float4 av = *(const float4*)(g_h1all + a_off + k0 + lk);
        float4 bv = *(const float4*)(Wo + b_off + k0 + lk);
        As[(lk + 0) * 64 + lr] = av.x; As[(lk + 1) * 64 + lr] = av.y;
        As[(lk + 2) * 64 + lr] = av.z; As[(lk + 3) * 64 + lr] = av.w;
        Bs[(lk + 0) * 64 + lr] = bv.x; Bs[(lk + 1) * 64 + lr] = bv.y;
        Bs[(lk + 2) * 64 + lr] = bv.z; Bs[(lk + 3) * 64 + lr] = bv.w;
        __syncthreads();
#pragma unroll
        for (int kk = 0; kk < 16; kk++) {
            float4 a = *(const float4*)(As + kk * 64 + tm);
            float4 b = *(const float4*)(Bs + kk * 64 + tn);
            FMA16();
        }
        __syncthreads();
    }
#pragma unroll
    for (int i = 0; i < 4; i++) {
        int m = bm + tm + i;
        int bb = m & 31;
        int s = m >> 5;
        size_t ro = ((size_t)bb * Ssz + s) * Osz;
#pragma unroll
        for (int j = 0; j < 4; j++) {
            int n = bn + tn + j;
            out[ro + n] = acc[i][j] + bo[n];
        }
    }
}

// ---------------- 32x32 tile GEMM (in-block 4-way K-split) ----------------
__device__ __forceinline__ void load_chunk(const float* __restrict__ Ap,
                                           const float* __restrict__ Wbase,
                                           int nrow0, int kk0,
                                           int u, float* As, float* Bs) {
#pragma unroll
    for (int r = 0; r < 2; r++) {
        int p = u + (r << 6);
        int mr = p >> 2;             // 0..31
        int kq = (p & 3) << 2;       // 0,4,8,12
        float4 av = *(const float4*)(Ap + mr * Hsz + kk0 + kq);
        As[(kq + 0) * 32 + mr] = av.x; As[(kq + 1) * 32 + mr] = av.y;
        As[(kq + 2) * 32 + mr] = av.z; As[(kq + 3) * 32 + mr] = av.w;
        float4 wv = *(const float4*)(Wbase + (size_t)(nrow0 + mr) * Hsz + kk0 + kq);
        Bs[(kq + 0) * 32 + mr] = wv.x; Bs[(kq + 1) * 32 + mr] = wv.y;
        Bs[(kq + 2) * 32 + mr] = wv.z; Bs[(kq + 3) * 32 + mr] = wv.w;
    }
}

__device__ __forceinline__ void compute_chunk(const float* As, const float* Bs,
                                              int tm, int tn, float acc[4][4]) {
#pragma unroll
    for (int kk = 0; kk < 16; kk++) {
        float4 a = *(const float4*)(As + kk * 32 + tm);
        float4 b = *(const float4*)(Bs + kk * 32 + tn);
        FMA16();
    }
}

// Compute 32x32 tile of Ap(32xK) @ W(rows n0..n0+31, stride Hsz)^T over
// K range [kbase, kbase+klen). Result summed across the 4 thread-groups
// lands in sm[q*1024 + m*32 + n], q=0..3 (caller sums the 4).
__device__ __forceinline__ void tile_accum(const float* __restrict__ Ap,
                                           const float* __restrict__ Wb,
                                           int n0, int kbase, int klen,
                                           int g, int u, int tm, int tn,
                                           float* As, float* Bs, float* sm) {
    float acc[4][4] = {};
    const int kslice = klen >> 2;
    const int kb = kbase + g * kslice;
    for (int kc = 0; kc < kslice; kc += 16) {
        load_chunk(Ap, Wb, n0, kb + kc, u, As, Bs);
        __syncthreads();
        compute_chunk(As, Bs, tm, tn, acc);
        __syncthreads();
    }
#pragma unroll
    for (int i = 0; i < 4; i++)
#pragma unroll
        for (int j = 0; j < 4; j++)
            sm[(g << 10) + (tm + i) * 32 + (tn + j)] = acc[i][j];
    __syncthreads();
}

#define SM4(m, n) (sm[(m)*32+(n)] + sm[1024+(m)*32+(n)] + sm[2048+(m)*32+(n)] + sm[3072+(m)*32+(n)])

// ---------------- persistent recurrence kernel ----------------
__global__ __launch_bounds__(256, 1) void k_recur(const float* __restrict__ Wx,
                                                  const float* __restrict__ Wh,
                                                  const float* __restrict__ bxp) {
    __shared__ __align__(16) float sm[4096];
    const int tid = threadIdx.x;
    const int b = blockIdx.x;
    const int g = tid >> 6;
    const int u = tid & 63;
    float* As = sm + (g << 10);
    float* Bs = As + 512;
    const int tm = (u >> 3) << 2;
    const int tn = (u & 7) << 2;
    unsigned bar = 0;

    for (int t = 0; t < Ssz; t++) {
        const float* xp = g_xp0 + (size_t)t * Bsz * 3072;

        // ---- Phase A: L0 z,r gates + L1 raw Wh z,r projections (128 tasks) ----
        if (b < 128) {
            const int sel = b >> 5;            // 0:z0 1:r0 2:pz1 3:pr1
            const int n0 = (b & 31) << 5;
            const float* Ap = (sel < 2) ? g_h0 : g_h1;
            const int widx = (sel == 0) ? 0 : (sel == 1) ? 1 : (sel == 2) ? 3 : 4;
            tile_accum(Ap, Wh + (size_t)widx * 1048576, n0, 0, 1024, g, u, tm, tn, As, Bs, sm);
#pragma unroll
            for (int jj = 0; jj < 4; jj++) {
                int o = tid + (jj << 8);
                int m = o >> 5, n = o & 31;
                float v = SM4(m, n);
                int i = n0 + n;
                if (sel == 0)      g_z0[m * Hsz + i] = sigf(v + xp[m * 3072 + i]);
                else if (sel == 1) g_rh0[m * Hsz + i] = sigf(v + xp[m * 3072 + 1024 + i]) * g_h0[m * Hsz + i];
                else if (sel == 2) g_pz1[m * Hsz + i] = v;
                else               g_pr1[m * Hsz + i] = v;
            }
        }
        gridbar(++bar);

        // ---- Phase B: L0 candidate GEMM partials (cross-block K-split 4) ----
        if (b < 128) {
            const int n0 = (b >> 2) << 5;
            const int s = b & 3;
            tile_accum(g_rh0, Wh + (size_t)2 * 1048576, n0, s << 8, 256, g, u, tm, tn, As, Bs, sm);
#pragma unroll
            for (int jj = 0; jj < 4; jj++) {
                int o = tid + (jj << 8);
                int m = o >> 5, n = o & 31;
                g_partB[(s << 15) + m * Hsz + n0 + n] = SM4(m, n);
            }
        }
        gridbar(++bar);

        // ---- Phase B2: h0 state update (elementwise) ----
        {
            int idx = b * 256 + tid;
            if (idx < Bsz * Hsz) {
                int m = idx >> 10;
                int i = idx & 1023;
                float p = g_partB[idx] + g_partB[32768 + idx] + g_partB[65536 + idx] + g_partB[98304 + idx]
                        + xp[m * 3072 + 2048 + i];
                float z = g_z0[idx];
                float h = g_h0[idx];
                g_h0[idx] = z * h + (1.f - z) * tanhf(p);
            }
        }
        gridbar(++bar);

        // ---- Phase C: L1 x-projections + gate fuse (96 tasks) ----
        if (b < 96) {
            const int gate = b >> 5;
            const int n0 = (b & 31) << 5;
            tile_accum(g_h0, Wx + (size_t)(3 + gate) * 1048576, n0, 0, 1024, g, u, tm, tn, As, Bs, sm);
#pragma unroll
            for (int jj = 0; jj < 4; jj++) {
                int o = tid + (jj << 8);
                int m = o >> 5, n = o & 31;
                float v = SM4(m, n);
                int i = n0 + n;
                float val = v + bxp[3072 + (gate << 10) + i];
                if (gate == 0)      g_z1[m * Hsz + i] = sigf(val + g_pz1[m * Hsz + i]);
                else if (gate == 1) g_rh1[m * Hsz + i] = sigf(val + g_pr1[m * Hsz + i]) * g_h1[m * Hsz + i];
                else                g_gc1[m * Hsz + i] = val;
            }
        }
        gridbar(++bar);

        // ---- Phase D: L1 candidate GEMM partials (cross-block K-split 4) ----
        if (b < 128) {
            const int n0 = (b >> 2) << 5;
            const int s = b & 3;
            tile_accum(g_rh1, Wh + (size_t)5 * 1048576, n0, s << 8, 256, g, u, tm, tn, As, Bs, sm);
#pragma unroll
            for (int jj = 0; jj < 4; jj++) {
                int o = tid + (jj << 8);
                int m = o >> 5, n = o & 31;
                g_partD[(s << 15) + m * Hsz + n0 + n] = SM4(m, n);
            }
        }
        gridbar(++bar);

        // ---- Phase D2: h1 state update + sequence store ----
        {
            int idx = b * 256 + tid;
            if (idx < Bsz * Hsz) {
                float p = g_partD[idx] + g_partD[32768 + idx] + g_partD[65536 + idx] + g_partD[98304 + idx]
                        + g_gc1[idx];
                float z = g_z1[idx];
                float h = g_h1[idx];
                float hn = z * h + (1.f - z) * tanhf(p);
                g_h1[idx] = hn;
                g_h1all[(size_t)t * Bsz * Hsz + idx] = hn;
            }
        }
        gridbar(++bar);
    }
}

// ---- final hidden state (B,L,H) appended after layer_output ----
__global__ void k_hid(float* __restrict__ out) {
    int idx = blockIdx.x * blockDim.x + threadIdx.x;  // 0..65535
    int b = idx >> 11;
    int r = idx & 2047;
    int l = r >> 10;
    int i = r & 1023;
    out[(size_t)Bsz * Ssz * Osz + idx] = (l == 0 ? g_h0 : g_h1)[b * Hsz + i];
}

// ---------------- launch (5 graph nodes total) ----------------
extern "C" void kernel_launch(void* const* d_in, const int* in_sizes, int n_in,
                              void* d_out, int out_size) {
    const float* x   = (const float*)d_in[0];
    const float* h0  = (const float*)d_in[1];
    const float* Wx  = (const float*)d_in[2];
    const float* Wh  = (const float*)d_in[3];
    const float* bx  = (const float*)d_in[4];
    const float* Wo  = (const float*)d_in[5];
    const float* bo  = (const float*)d_in[6];
    float* out = (float*)d_out;

    k_init<<<64, 1024>>>(h0);
    k_xproj<<<dim3(48, 256), 256>>>(x, Wx, bx);
    k_recur<<<GRID, 256>>>(Wx, Wh, bx);
    k_out<<<dim3(16, 256), 256>>>(Wo, bo, out);
    k_hid<<<64, 1024>>>(out);
}